// round 9
// baseline (speedup 1.0000x reference)
#include <cuda_runtime.h>
#include <cuda_bf16.h>
#include <cstdint>

// Problem dims
#define Bb  64
#define Tt  512
#define Hh  1024
#define INn 1024
#define BT  32768   // Bb*Tt
#define BH  65536   // Bb*Hh

// ---------------- static device scratch (no dynamic allocation allowed) -----
__device__ __nv_bfloat16 g_xh[(size_t)BT * INn];       // x hi  (64 MB)
__device__ __nv_bfloat16 g_xl[(size_t)BT * INn];       // x lo  (64 MB)
__device__ __nv_bfloat16 g_wh[4ull * Hh * INn];        // proj W hi (f,i,o,c)
__device__ __nv_bfloat16 g_wl[4ull * Hh * INn];        // proj W lo
__device__ __nv_bfloat16 g_rwh[3ull * Hh * Hh];        // rec W hi (f,i,o)
__device__ __nv_bfloat16 g_rwl[3ull * Hh * Hh];        // rec W lo
__device__ float         g_bias[4 * Hh];               // bcf,bci,bco,bxc
__device__ float         g_P[4ull * Tt * Bb * Hh];     // preacts [g][t][b][h] (512 MB)
__device__ __nv_bfloat16 g_cth[2][BH];                 // ct hi, double buffered
__device__ __nv_bfloat16 g_ctl[2][BH];                 // ct lo
__device__ unsigned      g_bar[640];                   // grid-barrier counters

// ---------------- helpers ----------------
__device__ __forceinline__ float sigf(float v) { return 1.0f / (1.0f + __expf(-v)); }

// D += A*B, m16n8k16 row.col, bf16 in / f32 acc
__device__ __forceinline__ void mma_bf16(float c[4], const unsigned a[4], const unsigned b[2]) {
    asm volatile(
        "mma.sync.aligned.m16n8k16.row.col.f32.bf16.bf16.f32 "
        "{%0,%1,%2,%3},{%4,%5,%6,%7},{%8,%9},{%0,%1,%2,%3};\n"
        : "+f"(c[0]), "+f"(c[1]), "+f"(c[2]), "+f"(c[3])
        : "r"(a[0]), "r"(a[1]), "r"(a[2]), "r"(a[3]), "r"(b[0]), "r"(b[1]));
}

__device__ __forceinline__ void grid_barrier(int slot) {
    __syncthreads();
    if (threadIdx.x == 0) {
        __threadfence();
        unsigned n = gridDim.x;
        if (atomicAdd(&g_bar[slot], 1u) + 1u < n) {
            while (*(volatile unsigned*)&g_bar[slot] < n) __nanosleep(64);
        }
        __threadfence();
    }
    __syncthreads();
}

// ---------------- setup kernels ----------------
__global__ void k_init() {
    if (threadIdx.x < 640) g_bar[threadIdx.x] = 0u;
}

__global__ void k_split_x(const float* __restrict__ x) {
    const size_t n4 = (size_t)BT * INn / 4;
    const size_t stride = (size_t)gridDim.x * blockDim.x;
    for (size_t i = (size_t)blockIdx.x * blockDim.x + threadIdx.x; i < n4; i += stride) {
        float4 v = ((const float4*)x)[i];
        __nv_bfloat16 h0 = __float2bfloat16(v.x), h1 = __float2bfloat16(v.y);
        __nv_bfloat16 h2 = __float2bfloat16(v.z), h3 = __float2bfloat16(v.w);
        __nv_bfloat16 l0 = __float2bfloat16(v.x - __bfloat162float(h0));
        __nv_bfloat16 l1 = __float2bfloat16(v.y - __bfloat162float(h1));
        __nv_bfloat16 l2 = __float2bfloat16(v.z - __bfloat162float(h2));
        __nv_bfloat16 l3 = __float2bfloat16(v.w - __bfloat162float(h3));
        ushort4 hv = make_ushort4(__bfloat16_as_ushort(h0), __bfloat16_as_ushort(h1),
                                  __bfloat16_as_ushort(h2), __bfloat16_as_ushort(h3));
        ushort4 lv = make_ushort4(__bfloat16_as_ushort(l0), __bfloat16_as_ushort(l1),
                                  __bfloat16_as_ushort(l2), __bfloat16_as_ushort(l3));
        ((ushort4*)g_xh)[i] = hv;
        ((ushort4*)g_xl)[i] = lv;
    }
}

// sel=0 -> g_wh/g_wl, sel=1 -> g_rwh/g_rwl ; off in elements (multiple of 4)
__global__ void k_split_w(const float* __restrict__ src, int sel, size_t off, size_t n4) {
    __nv_bfloat16* dh = sel ? g_rwh : g_wh;
    __nv_bfloat16* dl = sel ? g_rwl : g_wl;
    const size_t stride = (size_t)gridDim.x * blockDim.x;
    for (size_t i = (size_t)blockIdx.x * blockDim.x + threadIdx.x; i < n4; i += stride) {
        float4 v = ((const float4*)src)[i];
        __nv_bfloat16 h0 = __float2bfloat16(v.x), h1 = __float2bfloat16(v.y);
        __nv_bfloat16 h2 = __float2bfloat16(v.z), h3 = __float2bfloat16(v.w);
        __nv_bfloat16 l0 = __float2bfloat16(v.x - __bfloat162float(h0));
        __nv_bfloat16 l1 = __float2bfloat16(v.y - __bfloat162float(h1));
        __nv_bfloat16 l2 = __float2bfloat16(v.z - __bfloat162float(h2));
        __nv_bfloat16 l3 = __float2bfloat16(v.w - __bfloat162float(h3));
        ushort4 hv = make_ushort4(__bfloat16_as_ushort(h0), __bfloat16_as_ushort(h1),
                                  __bfloat16_as_ushort(h2), __bfloat16_as_ushort(h3));
        ushort4 lv = make_ushort4(__bfloat16_as_ushort(l0), __bfloat16_as_ushort(l1),
                                  __bfloat16_as_ushort(l2), __bfloat16_as_ushort(l3));
        ((ushort4*)(dh + off))[i] = hv;
        ((ushort4*)(dl + off))[i] = lv;
    }
}

__global__ void k_bias(const float* __restrict__ bf, const float* __restrict__ bi,
                       const float* __restrict__ bo, const float* __restrict__ bc) {
    int i = blockIdx.x * blockDim.x + threadIdx.x;
    if (i < Hh) {
        g_bias[i]          = bf[i];
        g_bias[Hh + i]     = bi[i];
        g_bias[2 * Hh + i] = bo[i];
        g_bias[3 * Hh + i] = bc[i];
    }
}

// ---------------- projection GEMM: P[g][t][b][h] = x @ Wx^T + bias ----------
// C tile 128x128, 8 warps (2x4), warp tile 64x32, K-chunk 32. 3-product split.
__global__ void __launch_bounds__(256) k_proj() {
    __shared__ __nv_bfloat16 sAh[128 * 40], sAl[128 * 40], sBh[128 * 40], sBl[128 * 40];
    const int bn = blockIdx.x;              // 0..31  (N tiles, fastest -> A reuse in L2)
    const int bm = blockIdx.y;              // 0..255 (M tiles)
    const int tid = threadIdx.x;
    const int wid = tid >> 5, lane = tid & 31;
    const int wm = wid >> 2, wn = wid & 3;
    const int grp = lane >> 2, tg = lane & 3;

    float acc[4][4][4];
#pragma unroll
    for (int mt = 0; mt < 4; ++mt)
#pragma unroll
        for (int nt = 0; nt < 4; ++nt)
#pragma unroll
            for (int r = 0; r < 4; ++r) acc[mt][nt][r] = 0.f;

    const unsigned* gxh = (const unsigned*)g_xh;
    const unsigned* gxl = (const unsigned*)g_xl;
    const unsigned* gwh = (const unsigned*)g_wh;
    const unsigned* gwl = (const unsigned*)g_wl;
    const int lr = tid >> 4;   // 0..15
    const int lc = tid & 15;   // 0..15 (uint cols)

    for (int kc = 0; kc < 32; ++kc) {
#pragma unroll
        for (int i = 0; i < 8; ++i) {
            int row = lr + 16 * i;
            size_t ga = (size_t)(bm * 128 + row) * 512 + kc * 16 + lc;
            size_t gb = (size_t)(bn * 128 + row) * 512 + kc * 16 + lc;
            ((unsigned*)sAh)[row * 20 + lc] = gxh[ga];
            ((unsigned*)sAl)[row * 20 + lc] = gxl[ga];
            ((unsigned*)sBh)[row * 20 + lc] = gwh[gb];
            ((unsigned*)sBl)[row * 20 + lc] = gwl[gb];
        }
        __syncthreads();
#pragma unroll
        for (int kk = 0; kk < 2; ++kk) {
            unsigned ah[4][4], al[4][4], bhf[4][2], blf[4][2];
            const int c0 = kk * 16 + tg * 2;
#pragma unroll
            for (int mt = 0; mt < 4; ++mt) {
                int r0 = wm * 64 + mt * 16 + grp;
                ah[mt][0] = *(const unsigned*)&sAh[r0 * 40 + c0];
                ah[mt][1] = *(const unsigned*)&sAh[(r0 + 8) * 40 + c0];
                ah[mt][2] = *(const unsigned*)&sAh[r0 * 40 + c0 + 8];
                ah[mt][3] = *(const unsigned*)&sAh[(r0 + 8) * 40 + c0 + 8];
                al[mt][0] = *(const unsigned*)&sAl[r0 * 40 + c0];
                al[mt][1] = *(const unsigned*)&sAl[(r0 + 8) * 40 + c0];
                al[mt][2] = *(const unsigned*)&sAl[r0 * 40 + c0 + 8];
                al[mt][3] = *(const unsigned*)&sAl[(r0 + 8) * 40 + c0 + 8];
            }
#pragma unroll
            for (int nt = 0; nt < 4; ++nt) {
                int br = wn * 32 + nt * 8 + grp;
                bhf[nt][0] = *(const unsigned*)&sBh[br * 40 + c0];
                bhf[nt][1] = *(const unsigned*)&sBh[br * 40 + c0 + 8];
                blf[nt][0] = *(const unsigned*)&sBl[br * 40 + c0];
                blf[nt][1] = *(const unsigned*)&sBl[br * 40 + c0 + 8];
            }
#pragma unroll
            for (int mt = 0; mt < 4; ++mt)
#pragma unroll
                for (int nt = 0; nt < 4; ++nt) {
                    mma_bf16(acc[mt][nt], ah[mt], bhf[nt]);
                    mma_bf16(acc[mt][nt], ah[mt], blf[nt]);
                    mma_bf16(acc[mt][nt], al[mt], bhf[nt]);
                }
        }
        __syncthreads();
    }
    // epilogue: scatter into [gate][t][b][h]
#pragma unroll
    for (int mt = 0; mt < 4; ++mt) {
#pragma unroll
        for (int nt = 0; nt < 4; ++nt) {
            int m0 = bm * 128 + wm * 64 + mt * 16 + grp;
            int n0 = bn * 128 + wn * 32 + nt * 8 + tg * 2;
            int g = n0 >> 10, h = n0 & 1023;
            float b0 = g_bias[n0], b1 = g_bias[n0 + 1];
#pragma unroll
            for (int e = 0; e < 2; ++e) {
                int m = m0 + 8 * e;
                int b = m >> 9, t = m & 511;
                size_t idx = (((size_t)g * Tt + t) * Bb + b) * Hh + h;
                float2 v;
                v.x = acc[mt][nt][2 * e] + b0;
                v.y = acc[mt][nt][2 * e + 1] + b1;
                *(float2*)&g_P[idx] = v;
            }
        }
    }
}

// ---------------- persistent recurrence kernel ------------------------------
// 128 CTAs x 128 threads. CTA j owns h in [8j, 8j+8), all 3 gates (24 cols).
// Weights (bf16 hi+lo, padded rows) cached in smem for all 512 steps.
__global__ void __launch_bounds__(128) k_rec(const float* __restrict__ c0,
                                             float* __restrict__ out_h,
                                             float* __restrict__ out_last) {
    extern __shared__ __nv_bfloat16 sw[];
    __nv_bfloat16* sWh = sw;
    __nv_bfloat16* sWl = sw + 24 * 1032;

    const int j = blockIdx.x;
    const int tid = threadIdx.x, wid = tid >> 5, lane = tid & 31;
    const int grp = lane >> 2, tg = lane & 3;
    const int h0 = j * 8;

    // load 24 weight rows (gate,hlocal) x 1024, hi+lo, padded stride 1032
    for (int idx = tid; idx < 24 * 512; idx += 128) {
        int r = idx >> 9, c = idx & 511;
        int g = r >> 3, hl = r & 7;
        size_t go = ((size_t)g * Hh + h0 + hl) * 512 + c;
        ((unsigned*)sWh)[r * 516 + c] = ((const unsigned*)g_rwh)[go];
        ((unsigned*)sWl)[r * 516 + c] = ((const unsigned*)g_rwl)[go];
    }

    const int brow = wid * 16 + grp;     // base batch row for this lane
    const int hl0 = tg * 2;              // base local h column
    float creg[4];                       // fp32 cell state: (b,h),(b,h+1),(b+8,h),(b+8,h+1)
    {
        float z0 = c0[h0 + hl0], z1 = c0[h0 + hl0 + 1];
        creg[0] = z0; creg[1] = z1; creg[2] = z0; creg[3] = z1;
#pragma unroll
        for (int e = 0; e < 2; ++e) {
            int b = brow + 8 * e;
            __nv_bfloat16 ch0 = __float2bfloat16(creg[2 * e]);
            __nv_bfloat16 ch1 = __float2bfloat16(creg[2 * e + 1]);
            __nv_bfloat16 cl0 = __float2bfloat16(creg[2 * e] - __bfloat162float(ch0));
            __nv_bfloat16 cl1 = __float2bfloat16(creg[2 * e + 1] - __bfloat162float(ch1));
            unsigned hv = (unsigned)__bfloat16_as_ushort(ch0) | ((unsigned)__bfloat16_as_ushort(ch1) << 16);
            unsigned lv = (unsigned)__bfloat16_as_ushort(cl0) | ((unsigned)__bfloat16_as_ushort(cl1) << 16);
            size_t off = ((size_t)b * Hh + h0 + hl0) >> 1;
            __stcg((unsigned*)g_cth[0] + off, hv);
            __stcg((unsigned*)g_ctl[0] + off, lv);
        }
    }
    __syncthreads();
    grid_barrier(0);

    const size_t GST = (size_t)Tt * Bb * Hh;   // gate stride in g_P

    for (int t = 0; t < Tt; ++t) {
        const int p = t & 1;
        const unsigned* Ah = (const unsigned*)g_cth[p];
        const unsigned* Al = (const unsigned*)g_ctl[p];
        float acc[3][4];
#pragma unroll
        for (int nt = 0; nt < 3; ++nt) { acc[nt][0] = acc[nt][1] = acc[nt][2] = acc[nt][3] = 0.f; }

#pragma unroll 4
        for (int ks = 0; ks < 64; ++ks) {
            const int k = ks * 16 + tg * 2;
            unsigned a_h[4], a_l[4];
            const unsigned o00 = (unsigned)((brow * Hh + k) >> 1);
            const unsigned o10 = (unsigned)(((brow + 8) * Hh + k) >> 1);
            a_h[0] = __ldcg(Ah + o00);
            a_h[1] = __ldcg(Ah + o10);
            a_h[2] = __ldcg(Ah + o00 + 4);
            a_h[3] = __ldcg(Ah + o10 + 4);
            a_l[0] = __ldcg(Al + o00);
            a_l[1] = __ldcg(Al + o10);
            a_l[2] = __ldcg(Al + o00 + 4);
            a_l[3] = __ldcg(Al + o10 + 4);
#pragma unroll
            for (int nt = 0; nt < 3; ++nt) {
                const int br = nt * 8 + grp;
                unsigned b_h[2], b_l[2];
                b_h[0] = *(const unsigned*)&sWh[br * 1032 + ks * 16 + tg * 2];
                b_h[1] = *(const unsigned*)&sWh[br * 1032 + ks * 16 + tg * 2 + 8];
                b_l[0] = *(const unsigned*)&sWl[br * 1032 + ks * 16 + tg * 2];
                b_l[1] = *(const unsigned*)&sWl[br * 1032 + ks * 16 + tg * 2 + 8];
                mma_bf16(acc[nt], a_h, b_h);
                mma_bf16(acc[nt], a_h, b_l);
                mma_bf16(acc[nt], a_l, b_h);
            }
        }

        // elementwise update for this lane's 4 cells
        const int pn = p ^ 1;
#pragma unroll
        for (int e = 0; e < 2; ++e) {
            int b = brow + 8 * e;
            size_t pidx = (((size_t)t) * Bb + b) * Hh + h0 + hl0;   // gate f (g=0)
            float2 Pf = *(const float2*)&g_P[pidx];
            float2 Pi = *(const float2*)&g_P[pidx + GST];
            float2 Po = *(const float2*)&g_P[pidx + 2 * GST];
            float2 Pc = *(const float2*)&g_P[pidx + 3 * GST];
            float f0 = sigf(acc[0][2 * e] + Pf.x);
            float f1 = sigf(acc[0][2 * e + 1] + Pf.y);
            float i0 = sigf(acc[1][2 * e] + Pi.x);
            float i1 = sigf(acc[1][2 * e + 1] + Pi.y);
            float o0 = sigf(acc[2][2 * e] + Po.x);
            float o1 = sigf(acc[2][2 * e + 1] + Po.y);
            float c0n = f0 * creg[2 * e] + i0 * tanhf(Pc.x);
            float c1n = f1 * creg[2 * e + 1] + i1 * tanhf(Pc.y);
            creg[2 * e] = c0n; creg[2 * e + 1] = c1n;

            __nv_bfloat16 ch0 = __float2bfloat16(c0n), ch1 = __float2bfloat16(c1n);
            __nv_bfloat16 cl0 = __float2bfloat16(c0n - __bfloat162float(ch0));
            __nv_bfloat16 cl1 = __float2bfloat16(c1n - __bfloat162float(ch1));
            unsigned hv = (unsigned)__bfloat16_as_ushort(ch0) | ((unsigned)__bfloat16_as_ushort(ch1) << 16);
            unsigned lv = (unsigned)__bfloat16_as_ushort(cl0) | ((unsigned)__bfloat16_as_ushort(cl1) << 16);
            size_t off = ((size_t)b * Hh + h0 + hl0) >> 1;
            __stcg((unsigned*)g_cth[pn] + off, hv);
            __stcg((unsigned*)g_ctl[pn] + off, lv);

            float2 hv2;
            hv2.x = o0 * tanhf(c0n);
            hv2.y = o1 * tanhf(c1n);
            *(float2*)&out_h[((size_t)b * Tt + t) * Hh + h0 + hl0] = hv2;
            if (out_last != nullptr && t == Tt - 1) {
                *(float2*)&out_last[(size_t)b * Hh + h0 + hl0] = hv2;
            }
        }
        grid_barrier(t + 1);
    }
}

// ---------------- launch --------------------------------------------------
extern "C" void kernel_launch(void* const* d_in, const int* in_sizes, int n_in,
                              void* d_out, int out_size) {
    const float* x   = (const float*)d_in[0];
    const float* Wxf = (const float*)d_in[1];
    const float* Wcf = (const float*)d_in[2];
    const float* bcf = (const float*)d_in[3];
    const float* Wxi = (const float*)d_in[4];
    const float* Wci = (const float*)d_in[5];
    const float* bci = (const float*)d_in[6];
    const float* Wxo = (const float*)d_in[7];
    const float* Wco = (const float*)d_in[8];
    const float* bco = (const float*)d_in[9];
    const float* Wxc = (const float*)d_in[10];
    const float* bxc = (const float*)d_in[11];
    const float* c0  = (const float*)d_in[12];
    float* out = (float*)d_out;

    const long long hid_elems = (long long)Bb * Tt * Hh;          // 33,554,432
    float* out_last = ((long long)out_size >= hid_elems + (long long)Bb * Hh)
                          ? out + hid_elems : nullptr;

    const int rec_smem = 24 * 1032 * 2 * 2;   // 99,072 B (hi+lo weight slices)
    cudaFuncSetAttribute(k_rec, cudaFuncAttributeMaxDynamicSharedMemorySize, rec_smem);

    k_init<<<1, 640>>>();
    k_split_x<<<2048, 256>>>(x);
    const size_t MW4 = (size_t)Hh * INn / 4;
    k_split_w<<<512, 256>>>(Wxf, 0, 0,                      MW4);
    k_split_w<<<512, 256>>>(Wxi, 0, (size_t)1 * Hh * INn,   MW4);
    k_split_w<<<512, 256>>>(Wxo, 0, (size_t)2 * Hh * INn,   MW4);
    k_split_w<<<512, 256>>>(Wxc, 0, (size_t)3 * Hh * INn,   MW4);
    k_split_w<<<512, 256>>>(Wcf, 1, 0,                      MW4);
    k_split_w<<<512, 256>>>(Wci, 1, (size_t)1 * Hh * Hh,    MW4);
    k_split_w<<<512, 256>>>(Wco, 1, (size_t)2 * Hh * Hh,    MW4);
    k_bias<<<4, 256>>>(bcf, bci, bco, bxc);
    k_proj<<<dim3(32, 256), 256>>>();
    k_rec<<<128, 128, rec_smem>>>(c0, out, out_last);
}